// round 1
// baseline (speedup 1.0000x reference)
#include <cuda_runtime.h>
#include <math.h>

#define NSAMP 4096
#define DIN   1536
#define DMLP  512
#define FD    256
#define NCLS  10000

// ---- static device scratch (no allocations allowed) ----
__device__ float g_h[NSAMP * DMLP];        // encoder hidden, pre-BN
__device__ float g_psum[64 * DMLP];        // BN partial sums
__device__ float g_psq[64 * DMLP];         // BN partial sum-of-squares
__device__ float g_scale[DMLP];            // gamma * rsqrt(var+eps)
__device__ float g_shift[DMLP];            // beta - mu*scale
__device__ float g_feat[NSAMP * FD];       // normalized encoder output
__device__ float g_mem[NCLS * FD];         // updated memory bank

// ============================================================
// GEMM1: g_h[4096,512] = feat_in[4096,1536] @ W1[1536,512] + b1
// classic 128x128x8 SGEMM, 8x8 per thread, 256 threads
// ============================================================
__global__ __launch_bounds__(256) void gemm1_kernel(
    const float* __restrict__ A, const float* __restrict__ B,
    const float* __restrict__ bias)
{
    __shared__ float As[8][128];
    __shared__ float Bs[8][128];
    const int tid = threadIdx.x;
    const int bm = blockIdx.y * 128, bn = blockIdx.x * 128;
    const int tx = tid & 15, ty = tid >> 4;
    const int a_r = tid >> 1, a_c = (tid & 1) << 2;
    const int b_k = tid >> 5, b_n = (tid & 31) << 2;

    float acc[8][8];
#pragma unroll
    for (int i = 0; i < 8; i++)
#pragma unroll
        for (int j = 0; j < 8; j++) acc[i][j] = 0.f;

    for (int k0 = 0; k0 < DIN; k0 += 8) {
        float4 av = *(const float4*)(A + (size_t)(bm + a_r) * DIN + k0 + a_c);
        As[a_c + 0][a_r] = av.x; As[a_c + 1][a_r] = av.y;
        As[a_c + 2][a_r] = av.z; As[a_c + 3][a_r] = av.w;
        *(float4*)&Bs[b_k][b_n] =
            *(const float4*)(B + (size_t)(k0 + b_k) * DMLP + bn + b_n);
        __syncthreads();
#pragma unroll
        for (int kk = 0; kk < 8; kk++) {
            float4 ra0 = *(float4*)&As[kk][ty * 8];
            float4 ra1 = *(float4*)&As[kk][ty * 8 + 4];
            float4 rb0 = *(float4*)&Bs[kk][tx * 8];
            float4 rb1 = *(float4*)&Bs[kk][tx * 8 + 4];
            float ra[8] = {ra0.x, ra0.y, ra0.z, ra0.w, ra1.x, ra1.y, ra1.z, ra1.w};
            float rb[8] = {rb0.x, rb0.y, rb0.z, rb0.w, rb1.x, rb1.y, rb1.z, rb1.w};
#pragma unroll
            for (int i = 0; i < 8; i++)
#pragma unroll
                for (int j = 0; j < 8; j++) acc[i][j] += ra[i] * rb[j];
        }
        __syncthreads();
    }
#pragma unroll
    for (int i = 0; i < 8; i++) {
        int r = bm + ty * 8 + i;
        int c0 = bn + tx * 8;
        float4 o0 = make_float4(acc[i][0] + bias[c0 + 0], acc[i][1] + bias[c0 + 1],
                                acc[i][2] + bias[c0 + 2], acc[i][3] + bias[c0 + 3]);
        float4 o1 = make_float4(acc[i][4] + bias[c0 + 4], acc[i][5] + bias[c0 + 5],
                                acc[i][6] + bias[c0 + 6], acc[i][7] + bias[c0 + 7]);
        *(float4*)&g_h[(size_t)r * DMLP + c0]     = o0;
        *(float4*)&g_h[(size_t)r * DMLP + c0 + 4] = o1;
    }
}

// ============================================================
// BN stats: 64 blocks x 512 threads, each block sums 64 rows (deterministic)
// ============================================================
__global__ __launch_bounds__(512) void bn_partial_kernel()
{
    const int b = blockIdx.x, c = threadIdx.x;
    float s = 0.f, ss = 0.f;
#pragma unroll 4
    for (int r = 0; r < 64; r++) {
        float v = g_h[(size_t)(b * 64 + r) * DMLP + c];
        s += v; ss += v * v;
    }
    g_psum[b * DMLP + c] = s;
    g_psq[b * DMLP + c] = ss;
}

__global__ __launch_bounds__(512) void bn_final_kernel(
    const float* __restrict__ gamma, const float* __restrict__ beta)
{
    const int c = threadIdx.x;
    float s = 0.f, ss = 0.f;
#pragma unroll 4
    for (int b = 0; b < 64; b++) { s += g_psum[b * DMLP + c]; ss += g_psq[b * DMLP + c]; }
    float mu = s * (1.0f / NSAMP);
    float var = ss * (1.0f / NSAMP) - mu * mu;
    float sc = gamma[c] * rsqrtf(var + 1e-5f);
    g_scale[c] = sc;
    g_shift[c] = beta[c] - mu * sc;
}

// ============================================================
// GEMM2 + row L2-norm: feat[4096,256] = l2norm(relu(BN(h)) @ W2 + b2)
// one block per 16 rows, 256 threads (thread = output column)
// ============================================================
__global__ __launch_bounds__(256) void gemm2_norm_kernel(
    const float* __restrict__ W2, const float* __restrict__ b2)
{
    __shared__ float sh[16][DMLP];   // 32 KB, BN+ReLU hidden rows
    __shared__ float so[16][FD];     // 16 KB, raw outputs
    __shared__ float snorm[16];
    const int tid = threadIdx.x;
    const int r0 = blockIdx.x * 16;

    for (int idx = tid; idx < 16 * DMLP; idx += 256) {
        int r = idx >> 9, c = idx & (DMLP - 1);
        float v = g_h[(size_t)(r0 + r) * DMLP + c] * g_scale[c] + g_shift[c];
        sh[r][c] = fmaxf(v, 0.f);
    }
    __syncthreads();

    const int c = tid;
    float acc[16];
#pragma unroll
    for (int r = 0; r < 16; r++) acc[r] = 0.f;
    const float* w2c = W2 + c;
#pragma unroll 4
    for (int k = 0; k < DMLP; k++) {
        float w = w2c[(size_t)k * FD];
#pragma unroll
        for (int r = 0; r < 16; r++) acc[r] += sh[r][k] * w;
    }
    float bc = b2[c];
#pragma unroll
    for (int r = 0; r < 16; r++) so[r][c] = acc[r] + bc;
    __syncthreads();

    // per-row sumsq: 8 warps, warp w handles rows 2w, 2w+1
    const int w = tid >> 5, lane = tid & 31;
#pragma unroll
    for (int rr = 2 * w; rr <= 2 * w + 1; rr++) {
        float ssq = 0.f;
#pragma unroll
        for (int j = 0; j < 8; j++) { float v = so[rr][lane + j * 32]; ssq += v * v; }
#pragma unroll
        for (int o = 16; o; o >>= 1) ssq += __shfl_xor_sync(0xffffffffu, ssq, o);
        if (lane == 0) snorm[rr] = sqrtf(ssq);
    }
    __syncthreads();
#pragma unroll
    for (int r = 0; r < 16; r++) {
        float inv = 1.0f / fmaxf(snorm[r], 1e-12f);
        g_feat[(size_t)(r0 + r) * FD + c] = so[r][c] * inv;
    }
}

// ============================================================
// Memory update: recurrence decomposes per label row.
// One warp per memory row; ballot-scan labels in order; replay updates.
// ============================================================
__global__ __launch_bounds__(256) void memupd_kernel(
    const int* __restrict__ label, const float* __restrict__ mem0)
{
    __shared__ int sl[NSAMP];
    const int tid = threadIdx.x;
    for (int i = tid; i < NSAMP; i += 256) sl[i] = label[i];
    __syncthreads();

    const int w = tid >> 5, lane = tid & 31;
    const int k = blockIdx.x * 8 + w;
    if (k >= NCLS) return;

    float pt[8];
#pragma unroll
    for (int j = 0; j < 8; j++) pt[j] = mem0[(size_t)k * FD + lane + j * 32];

    for (int base = 0; base < NSAMP; base += 32) {
        unsigned m = __ballot_sync(0xffffffffu, sl[base + lane] == k);
        while (m) {
            int b = __ffs(m) - 1;
            m &= m - 1;
            const float* f = g_feat + (size_t)(base + b) * FD;
            float ssq = 0.f;
#pragma unroll
            for (int j = 0; j < 8; j++) {
                pt[j] = 0.9f * pt[j] + 0.1f * f[lane + j * 32];
                ssq += pt[j] * pt[j];
            }
#pragma unroll
            for (int o = 16; o; o >>= 1) ssq += __shfl_xor_sync(0xffffffffu, ssq, o);
            float inv = 1.0f / fmaxf(sqrtf(ssq), 1e-12f);
#pragma unroll
            for (int j = 0; j < 8; j++) pt[j] *= inv;
        }
    }
#pragma unroll
    for (int j = 0; j < 8; j++) g_mem[(size_t)k * FD + lane + j * 32] = pt[j];
}

// ============================================================
// Sim GEMM: out[4096,10000] = feat[4096,256] @ mem[10000,256]^T  (NT)
// 128x128x8 SGEMM with transposed B-tile load, bounds on N
// ============================================================
__global__ __launch_bounds__(256) void sim_gemm_kernel(float* __restrict__ C)
{
    __shared__ float As[8][128];
    __shared__ float Bs[8][128];
    const int tid = threadIdx.x;
    const int bm = blockIdx.y * 128, bn = blockIdx.x * 128;
    const int tx = tid & 15, ty = tid >> 4;
    const int a_r = tid >> 1, a_c = (tid & 1) << 2;   // reused for B (n-row, k-group)

    float acc[8][8];
#pragma unroll
    for (int i = 0; i < 8; i++)
#pragma unroll
        for (int j = 0; j < 8; j++) acc[i][j] = 0.f;

    for (int k0 = 0; k0 < FD; k0 += 8) {
        float4 av = *(const float4*)(g_feat + (size_t)(bm + a_r) * FD + k0 + a_c);
        As[a_c + 0][a_r] = av.x; As[a_c + 1][a_r] = av.y;
        As[a_c + 2][a_r] = av.z; As[a_c + 3][a_r] = av.w;
        int gn = bn + a_r;
        float4 bv = make_float4(0.f, 0.f, 0.f, 0.f);
        if (gn < NCLS) bv = *(const float4*)(g_mem + (size_t)gn * FD + k0 + a_c);
        Bs[a_c + 0][a_r] = bv.x; Bs[a_c + 1][a_r] = bv.y;
        Bs[a_c + 2][a_r] = bv.z; Bs[a_c + 3][a_r] = bv.w;
        __syncthreads();
#pragma unroll
        for (int kk = 0; kk < 8; kk++) {
            float4 ra0 = *(float4*)&As[kk][ty * 8];
            float4 ra1 = *(float4*)&As[kk][ty * 8 + 4];
            float4 rb0 = *(float4*)&Bs[kk][tx * 8];
            float4 rb1 = *(float4*)&Bs[kk][tx * 8 + 4];
            float ra[8] = {ra0.x, ra0.y, ra0.z, ra0.w, ra1.x, ra1.y, ra1.z, ra1.w};
            float rb[8] = {rb0.x, rb0.y, rb0.z, rb0.w, rb1.x, rb1.y, rb1.z, rb1.w};
#pragma unroll
            for (int i = 0; i < 8; i++)
#pragma unroll
                for (int j = 0; j < 8; j++) acc[i][j] += ra[i] * rb[j];
        }
        __syncthreads();
    }
#pragma unroll
    for (int i = 0; i < 8; i++) {
        int r = bm + ty * 8 + i;
        int c0 = bn + tx * 8;
        if (c0 < NCLS) {  // 10000 % 4 == 0 -> each float4 fully in or out
            *(float4*)&C[(size_t)r * NCLS + c0] =
                make_float4(acc[i][0], acc[i][1], acc[i][2], acc[i][3]);
        }
        if (c0 + 4 < NCLS) {
            *(float4*)&C[(size_t)r * NCLS + c0 + 4] =
                make_float4(acc[i][4], acc[i][5], acc[i][6], acc[i][7]);
        }
    }
}

// ============================================================
// launch
// inputs: 0 feat_in, 1 label, 2 W1, 3 b1, 4 gamma, 5 beta, 6 W2, 7 b2, 8 memory_pt
// ============================================================
extern "C" void kernel_launch(void* const* d_in, const int* in_sizes, int n_in,
                              void* d_out, int out_size)
{
    const float* feat_in = (const float*)d_in[0];
    const int*   label   = (const int*)d_in[1];
    const float* W1      = (const float*)d_in[2];
    const float* b1      = (const float*)d_in[3];
    const float* gamma   = (const float*)d_in[4];
    const float* beta    = (const float*)d_in[5];
    const float* W2      = (const float*)d_in[6];
    const float* b2      = (const float*)d_in[7];
    const float* mem0    = (const float*)d_in[8];
    float* out = (float*)d_out;

    gemm1_kernel<<<dim3(DMLP / 128, NSAMP / 128), 256>>>(feat_in, W1, b1);
    bn_partial_kernel<<<64, 512>>>();
    bn_final_kernel<<<1, 512>>>(gamma, beta);
    gemm2_norm_kernel<<<NSAMP / 16, 256>>>(W2, b2);
    memupd_kernel<<<(NCLS + 7) / 8, 256>>>(label, mem0);
    sim_gemm_kernel<<<dim3((NCLS + 127) / 128, NSAMP / 128), 256>>>(out);
}

// round 3
// speedup vs baseline: 1.6113x; 1.6113x over previous
#include <cuda_runtime.h>
#include <cuda_bf16.h>
#include <math.h>

#define NSAMP 4096
#define DIN   1536
#define DMLP  512
#define FD    256
#define NCLS  10000
#define KP1   (3*DIN)   // 4608, split-K' for gemm1
#define KPS   (3*FD)    // 768,  split-K' for sim gemm

// ---- static device scratch (referenced ONLY from device code) ----
__device__ float g_h[NSAMP * DMLP];
__device__ float g_psum[64 * DMLP];
__device__ float g_psq[64 * DMLP];
__device__ float g_scale[DMLP];
__device__ float g_shift[DMLP];
__device__ float g_feat[NSAMP * FD];
__device__ float g_mem[NCLS * FD];

__device__ __align__(16) __nv_bfloat16 g_A1[(size_t)NSAMP * KP1];    // [M][K'] = [Ah|Al|Ah]
__device__ __align__(16) __nv_bfloat16 g_B1[(size_t)DMLP * KP1];     // [N][K'] = [Bh|Bh|Bl]
__device__ __align__(16) __nv_bfloat16 g_feat2[(size_t)NSAMP * KPS]; // [Ah|Al|Ah]
__device__ __align__(16) __nv_bfloat16 g_mem2[(size_t)NCLS * KPS];   // [Bh|Bh|Bl]

// ============================================================
// split conversions
// ============================================================
__global__ void conv_A1_kernel(const float* __restrict__ A)
{
    int idx = blockIdx.x * 256 + threadIdx.x;
    if (idx >= NSAMP * DIN) return;
    int m = idx / DIN, k = idx - m * DIN;
    float x = A[idx];
    __nv_bfloat16 h = __float2bfloat16_rn(x);
    __nv_bfloat16 l = __float2bfloat16_rn(x - __bfloat162float(h));
    size_t base = (size_t)m * KP1;
    g_A1[base + k] = h;
    g_A1[base + DIN + k] = l;
    g_A1[base + 2 * DIN + k] = h;
}

__global__ void conv_B1_kernel(const float* __restrict__ W1)  // W1 [K=1536][N=512]
{
    int idx = blockIdx.x * 256 + threadIdx.x;
    if (idx >= DIN * DMLP) return;
    int k = idx / DMLP, n = idx - k * DMLP;
    float x = W1[idx];
    __nv_bfloat16 h = __float2bfloat16_rn(x);
    __nv_bfloat16 l = __float2bfloat16_rn(x - __bfloat162float(h));
    size_t base = (size_t)n * KP1;
    g_B1[base + k] = h;
    g_B1[base + DIN + k] = h;
    g_B1[base + 2 * DIN + k] = l;
}

__global__ void conv_feat2_kernel()
{
    int idx = blockIdx.x * 256 + threadIdx.x;
    if (idx >= NSAMP * FD) return;
    int m = idx / FD, k = idx - m * FD;
    float x = g_feat[idx];
    __nv_bfloat16 h = __float2bfloat16_rn(x);
    __nv_bfloat16 l = __float2bfloat16_rn(x - __bfloat162float(h));
    size_t base = (size_t)m * KPS;
    g_feat2[base + k] = h;
    g_feat2[base + FD + k] = l;
    g_feat2[base + 2 * FD + k] = h;
}

__global__ void conv_mem2_kernel()
{
    int idx = blockIdx.x * 256 + threadIdx.x;
    if (idx >= NCLS * FD) return;
    int n = idx / FD, k = idx - n * FD;
    float x = g_mem[idx];
    __nv_bfloat16 h = __float2bfloat16_rn(x);
    __nv_bfloat16 l = __float2bfloat16_rn(x - __bfloat162float(h));
    size_t base = (size_t)n * KPS;
    g_mem2[base + k] = h;
    g_mem2[base + FD + k] = h;
    g_mem2[base + 2 * FD + k] = l;
}

// ============================================================
// bf16 MMA GEMM: C[M,N] = A[M,K'] @ B[N,K']^T (+bias)
// BM=128, BK=32, 256 threads = 8 warps (2x4), warp tile 64 x (BN/4)
// SIM=false: A=g_A1, B=g_B1, C=g_h ;  SIM=true: A=g_feat2, B=g_mem2, C=param
// ============================================================
__device__ __forceinline__ void mma16816(float c[4],
    unsigned a0, unsigned a1, unsigned a2, unsigned a3,
    unsigned b0, unsigned b1)
{
    asm volatile(
        "mma.sync.aligned.m16n8k16.row.col.f32.bf16.bf16.f32 "
        "{%0,%1,%2,%3},{%4,%5,%6,%7},{%8,%9},{%0,%1,%2,%3};\n"
        : "+f"(c[0]), "+f"(c[1]), "+f"(c[2]), "+f"(c[3])
        : "r"(a0), "r"(a1), "r"(a2), "r"(a3), "r"(b0), "r"(b1));
}

template<int BN, int KP, int NK, bool SIM>
__global__ __launch_bounds__(256) void mma_gemm_kernel(
    float* __restrict__ Cout, const float* __restrict__ bias)
{
    constexpr int BM = 128, BK = 32;
    constexpr int LDS_ = BK + 8;          // 40 bf16 = 80B row stride
    constexpr int WTN = BN / 4;           // warp tile N
    constexpr int NTI = WTN / 8;          // n-tiles per warp
    constexpr int ACH = BM / 64;          // 16B-chunks per thread for A (=2)
    constexpr int BCH = (BN + 63) / 64;   // for B (1 or 2)
    constexpr int Nreal = SIM ? NCLS : DMLP;
    constexpr int ldc   = SIM ? NCLS : DMLP;

    const __nv_bfloat16* __restrict__ A = SIM ? g_feat2 : g_A1;
    const __nv_bfloat16* __restrict__ B = SIM ? g_mem2  : g_B1;
    float* __restrict__ C = SIM ? Cout : g_h;

    __shared__ __align__(16) __nv_bfloat16 As[BM * LDS_];
    __shared__ __align__(16) __nv_bfloat16 Bs[BN * LDS_];

    const int tid = threadIdx.x;
    const int wid = tid >> 5, lane = tid & 31;
    const int wm = wid >> 2, wn = wid & 3;
    const int bm = blockIdx.y * BM;
    const int bn = blockIdx.x * BN;
    const int g = lane >> 2, q2 = (lane & 3) * 2;

    uint4 pa[ACH], pb[BCH];

    auto loadA = [&](int kt) {
#pragma unroll
        for (int i = 0; i < ACH; i++) {
            int idx = tid + i * 256;
            int r = idx >> 2, kc = (idx & 3) * 8;
            pa[i] = *(const uint4*)(A + (size_t)(bm + r) * KP + kt * BK + kc);
        }
    };
    auto loadB = [&](int kt) {
#pragma unroll
        for (int i = 0; i < BCH; i++) {
            int idx = tid + i * 256;
            if (idx < BN * 4) {
                int r = idx >> 2, kc = (idx & 3) * 8;
                int gn = bn + r;
                if (!SIM || gn < Nreal)
                    pb[i] = *(const uint4*)(B + (size_t)gn * KP + kt * BK + kc);
                else
                    pb[i] = make_uint4(0u, 0u, 0u, 0u);
            }
        }
    };

    float acc[4][NTI][4];
#pragma unroll
    for (int i = 0; i < 4; i++)
#pragma unroll
        for (int j = 0; j < NTI; j++)
#pragma unroll
            for (int t = 0; t < 4; t++) acc[i][j][t] = 0.f;

    loadA(0); loadB(0);

    for (int kt = 0; kt < NK; kt++) {
#pragma unroll
        for (int i = 0; i < ACH; i++) {
            int idx = tid + i * 256;
            int r = idx >> 2, kc = (idx & 3) * 8;
            *(uint4*)(As + r * LDS_ + kc) = pa[i];
        }
#pragma unroll
        for (int i = 0; i < BCH; i++) {
            int idx = tid + i * 256;
            if (idx < BN * 4) {
                int r = idx >> 2, kc = (idx & 3) * 8;
                *(uint4*)(Bs + r * LDS_ + kc) = pb[i];
            }
        }
        __syncthreads();
        if (kt + 1 < NK) { loadA(kt + 1); loadB(kt + 1); }

#pragma unroll
        for (int ks = 0; ks < 2; ks++) {
            const int k0 = ks * 16 + q2;
            unsigned af[4][4];
#pragma unroll
            for (int i = 0; i < 4; i++) {
                int m0 = wm * 64 + i * 16 + g;
                af[i][0] = *(const unsigned*)(As + m0 * LDS_ + k0);
                af[i][1] = *(const unsigned*)(As + (m0 + 8) * LDS_ + k0);
                af[i][2] = *(const unsigned*)(As + m0 * LDS_ + k0 + 8);
                af[i][3] = *(const unsigned*)(As + (m0 + 8) * LDS_ + k0 + 8);
            }
            unsigned bfr[NTI][2];
#pragma unroll
            for (int j = 0; j < NTI; j++) {
                int n0 = wn * WTN + j * 8 + g;
                bfr[j][0] = *(const unsigned*)(Bs + n0 * LDS_ + k0);
                bfr[j][1] = *(const unsigned*)(Bs + n0 * LDS_ + k0 + 8);
            }
#pragma unroll
            for (int i = 0; i < 4; i++)
#pragma unroll
                for (int j = 0; j < NTI; j++)
                    mma16816(acc[i][j], af[i][0], af[i][1], af[i][2], af[i][3],
                             bfr[j][0], bfr[j][1]);
        }
        __syncthreads();
    }

#pragma unroll
    for (int i = 0; i < 4; i++) {
        int m0 = bm + wm * 64 + i * 16 + g;
#pragma unroll
        for (int j = 0; j < NTI; j++) {
            int n0 = bn + wn * WTN + j * 8 + q2;
            if (!SIM || n0 < Nreal) {
                float b0 = 0.f, b1 = 0.f;
                if (!SIM) { b0 = bias[n0]; b1 = bias[n0 + 1]; }
                *(float2*)(C + (size_t)m0 * ldc + n0) =
                    make_float2(acc[i][j][0] + b0, acc[i][j][1] + b1);
                *(float2*)(C + (size_t)(m0 + 8) * ldc + n0) =
                    make_float2(acc[i][j][2] + b0, acc[i][j][3] + b1);
            }
        }
    }
}

// ============================================================
// BN stats (deterministic two-stage)
// ============================================================
__global__ __launch_bounds__(512) void bn_partial_kernel()
{
    const int b = blockIdx.x, c = threadIdx.x;
    float s = 0.f, ss = 0.f;
#pragma unroll 4
    for (int r = 0; r < 64; r++) {
        float v = g_h[(size_t)(b * 64 + r) * DMLP + c];
        s += v; ss += v * v;
    }
    g_psum[b * DMLP + c] = s;
    g_psq[b * DMLP + c] = ss;
}

__global__ __launch_bounds__(512) void bn_final_kernel(
    const float* __restrict__ gamma, const float* __restrict__ beta)
{
    const int c = threadIdx.x;
    float s = 0.f, ss = 0.f;
#pragma unroll 4
    for (int b = 0; b < 64; b++) { s += g_psum[b * DMLP + c]; ss += g_psq[b * DMLP + c]; }
    float mu = s * (1.0f / NSAMP);
    float var = ss * (1.0f / NSAMP) - mu * mu;
    float sc = gamma[c] * rsqrtf(var + 1e-5f);
    g_scale[c] = sc;
    g_shift[c] = beta[c] - mu * sc;
}

// ============================================================
// GEMM2 + row L2-norm (fp32)
// ============================================================
__global__ __launch_bounds__(256) void gemm2_norm_kernel(
    const float* __restrict__ W2, const float* __restrict__ b2)
{
    __shared__ float sh[16][DMLP];
    __shared__ float so[16][FD];
    __shared__ float snorm[16];
    const int tid = threadIdx.x;
    const int r0 = blockIdx.x * 16;

    for (int idx = tid; idx < 16 * DMLP; idx += 256) {
        int r = idx >> 9, c = idx & (DMLP - 1);
        float v = g_h[(size_t)(r0 + r) * DMLP + c] * g_scale[c] + g_shift[c];
        sh[r][c] = fmaxf(v, 0.f);
    }
    __syncthreads();

    const int c = tid;
    float acc[16];
#pragma unroll
    for (int r = 0; r < 16; r++) acc[r] = 0.f;
    const float* w2c = W2 + c;
#pragma unroll 4
    for (int k = 0; k < DMLP; k++) {
        float w = w2c[(size_t)k * FD];
#pragma unroll
        for (int r = 0; r < 16; r++) acc[r] += sh[r][k] * w;
    }
    float bc = b2[c];
#pragma unroll
    for (int r = 0; r < 16; r++) so[r][c] = acc[r] + bc;
    __syncthreads();

    const int w = tid >> 5, lane = tid & 31;
#pragma unroll
    for (int rr = 2 * w; rr <= 2 * w + 1; rr++) {
        float ssq = 0.f;
#pragma unroll
        for (int j = 0; j < 8; j++) { float v = so[rr][lane + j * 32]; ssq += v * v; }
#pragma unroll
        for (int o = 16; o; o >>= 1) ssq += __shfl_xor_sync(0xffffffffu, ssq, o);
        if (lane == 0) snorm[rr] = sqrtf(ssq);
    }
    __syncthreads();
#pragma unroll
    for (int r = 0; r < 16; r++) {
        float inv = 1.0f / fmaxf(snorm[r], 1e-12f);
        g_feat[(size_t)(r0 + r) * FD + c] = so[r][c] * inv;
    }
}

// ============================================================
// Memory update: one warp per class row, in-order replay
// ============================================================
__global__ __launch_bounds__(256) void memupd_kernel(
    const int* __restrict__ label, const float* __restrict__ mem0)
{
    __shared__ int sl[NSAMP];
    const int tid = threadIdx.x;
    for (int i = tid; i < NSAMP; i += 256) sl[i] = label[i];
    __syncthreads();

    const int w = tid >> 5, lane = tid & 31;
    const int k = blockIdx.x * 8 + w;
    if (k >= NCLS) return;

    float pt[8];
#pragma unroll
    for (int j = 0; j < 8; j++) pt[j] = mem0[(size_t)k * FD + lane + j * 32];

    for (int base = 0; base < NSAMP; base += 32) {
        unsigned m = __ballot_sync(0xffffffffu, sl[base + lane] == k);
        while (m) {
            int b = __ffs(m) - 1;
            m &= m - 1;
            const float* f = g_feat + (size_t)(base + b) * FD;
            float ssq = 0.f;
#pragma unroll
            for (int j = 0; j < 8; j++) {
                pt[j] = 0.9f * pt[j] + 0.1f * f[lane + j * 32];
                ssq += pt[j] * pt[j];
            }
#pragma unroll
            for (int o = 16; o; o >>= 1) ssq += __shfl_xor_sync(0xffffffffu, ssq, o);
            float inv = 1.0f / fmaxf(sqrtf(ssq), 1e-12f);
#pragma unroll
            for (int j = 0; j < 8; j++) pt[j] *= inv;
        }
    }
#pragma unroll
    for (int j = 0; j < 8; j++) g_mem[(size_t)k * FD + lane + j * 32] = pt[j];
}

// ============================================================
// launch
// inputs: 0 feat_in, 1 label, 2 W1, 3 b1, 4 gamma, 5 beta, 6 W2, 7 b2, 8 memory_pt
// ============================================================
extern "C" void kernel_launch(void* const* d_in, const int* in_sizes, int n_in,
                              void* d_out, int out_size)
{
    const float* feat_in = (const float*)d_in[0];
    const int*   label   = (const int*)d_in[1];
    const float* W1      = (const float*)d_in[2];
    const float* b1      = (const float*)d_in[3];
    const float* gamma   = (const float*)d_in[4];
    const float* beta    = (const float*)d_in[5];
    const float* W2      = (const float*)d_in[6];
    const float* b2      = (const float*)d_in[7];
    const float* mem0    = (const float*)d_in[8];
    float* out = (float*)d_out;

    conv_A1_kernel<<<(NSAMP * DIN + 255) / 256, 256>>>(feat_in);
    conv_B1_kernel<<<(DIN * DMLP + 255) / 256, 256>>>(W1);

    // GEMM1: g_h = feat_in @ W1 + b1   (bf16 split-3)
    mma_gemm_kernel<64, KP1, KP1 / 32, false>
        <<<dim3(DMLP / 64, NSAMP / 128), 256>>>(nullptr, b1);

    bn_partial_kernel<<<64, 512>>>();
    bn_final_kernel<<<1, 512>>>(gamma, beta);
    gemm2_norm_kernel<<<NSAMP / 16, 256>>>(W2, b2);
    memupd_kernel<<<(NCLS + 7) / 8, 256>>>(label, mem0);

    conv_feat2_kernel<<<(NSAMP * FD + 255) / 256, 256>>>();
    conv_mem2_kernel<<<(NCLS * FD + 255) / 256, 256>>>();

    // Sim GEMM: out = feat @ mem^T   (bf16 split-3)
    mma_gemm_kernel<128, KPS, KPS / 32, true>
        <<<dim3((NCLS + 127) / 128, NSAMP / 128), 256>>>(out, nullptr);
}

// round 4
// speedup vs baseline: 2.0722x; 1.2861x over previous
#include <cuda_runtime.h>
#include <cuda_bf16.h>
#include <math.h>

#define NSAMP 4096
#define DIN   1536
#define DMLP  512
#define FD    256
#define NCLS  10000
#define KP1   (3*DIN)   // 4608
#define KP2   (3*DMLP)  // 1536
#define KPS   (3*FD)    // 768

// ---- static device scratch (device-code references only) ----
__device__ float g_h[NSAMP * DMLP];
__device__ float g_psum[256 * DMLP];
__device__ float g_psq[256 * DMLP];
__device__ float g_scale[DMLP];
__device__ float g_shift[DMLP];
__device__ float g_feat[NSAMP * FD];
__device__ float g_mem[NCLS * FD];

__device__ __align__(16) __nv_bfloat16 g_A1[(size_t)NSAMP * KP1];
__device__ __align__(16) __nv_bfloat16 g_B1[(size_t)DMLP * KP1];
__device__ __align__(16) __nv_bfloat16 g_A2[(size_t)NSAMP * KP2];
__device__ __align__(16) __nv_bfloat16 g_B2[(size_t)FD * KP2];
__device__ __align__(16) __nv_bfloat16 g_feat2[(size_t)NSAMP * KPS];
__device__ __align__(16) __nv_bfloat16 g_mem2[(size_t)NCLS * KPS];

// ============================================================
// split conversions
// ============================================================
__global__ void conv_A1_kernel(const float* __restrict__ A)
{
    int idx = blockIdx.x * 256 + threadIdx.x;
    if (idx >= NSAMP * DIN) return;
    int m = idx / DIN, k = idx - m * DIN;
    float x = A[idx];
    __nv_bfloat16 h = __float2bfloat16_rn(x);
    __nv_bfloat16 l = __float2bfloat16_rn(x - __bfloat162float(h));
    size_t base = (size_t)m * KP1;
    g_A1[base + k] = h;
    g_A1[base + DIN + k] = l;
    g_A1[base + 2 * DIN + k] = h;
}

__global__ void conv_B1_kernel(const float* __restrict__ W1)  // [1536][512]
{
    int idx = blockIdx.x * 256 + threadIdx.x;
    if (idx >= DIN * DMLP) return;
    int k = idx / DMLP, n = idx - k * DMLP;
    float x = W1[idx];
    __nv_bfloat16 h = __float2bfloat16_rn(x);
    __nv_bfloat16 l = __float2bfloat16_rn(x - __bfloat162float(h));
    size_t base = (size_t)n * KP1;
    g_B1[base + k] = h;
    g_B1[base + DIN + k] = h;
    g_B1[base + 2 * DIN + k] = l;
}

// BN + ReLU + split (A of gemm2)
__global__ void conv_A2_kernel()
{
    int idx = blockIdx.x * 256 + threadIdx.x;
    if (idx >= NSAMP * DMLP) return;
    int m = idx >> 9, c = idx & (DMLP - 1);
    float x = fmaxf(g_h[idx] * g_scale[c] + g_shift[c], 0.f);
    __nv_bfloat16 h = __float2bfloat16_rn(x);
    __nv_bfloat16 l = __float2bfloat16_rn(x - __bfloat162float(h));
    size_t base = (size_t)m * KP2;
    g_A2[base + c] = h;
    g_A2[base + DMLP + c] = l;
    g_A2[base + 2 * DMLP + c] = h;
}

__global__ void conv_B2_kernel(const float* __restrict__ W2)  // [512][256]
{
    int idx = blockIdx.x * 256 + threadIdx.x;
    if (idx >= DMLP * FD) return;
    int k = idx >> 8, n = idx & (FD - 1);
    float x = W2[idx];
    __nv_bfloat16 h = __float2bfloat16_rn(x);
    __nv_bfloat16 l = __float2bfloat16_rn(x - __bfloat162float(h));
    size_t base = (size_t)n * KP2;
    g_B2[base + k] = h;
    g_B2[base + DMLP + k] = h;
    g_B2[base + 2 * DMLP + k] = l;
}

__global__ void conv_feat2_kernel()
{
    int idx = blockIdx.x * 256 + threadIdx.x;
    if (idx >= NSAMP * FD) return;
    int m = idx >> 8, k = idx & (FD - 1);
    float x = g_feat[idx];
    __nv_bfloat16 h = __float2bfloat16_rn(x);
    __nv_bfloat16 l = __float2bfloat16_rn(x - __bfloat162float(h));
    size_t base = (size_t)m * KPS;
    g_feat2[base + k] = h;
    g_feat2[base + FD + k] = l;
    g_feat2[base + 2 * FD + k] = h;
}

__global__ void conv_mem2_kernel()
{
    int idx = blockIdx.x * 256 + threadIdx.x;
    if (idx >= NCLS * FD) return;
    int n = idx >> 8, k = idx & (FD - 1);
    float x = g_mem[idx];
    __nv_bfloat16 h = __float2bfloat16_rn(x);
    __nv_bfloat16 l = __float2bfloat16_rn(x - __bfloat162float(h));
    size_t base = (size_t)n * KPS;
    g_mem2[base + k] = h;
    g_mem2[base + FD + k] = h;
    g_mem2[base + 2 * FD + k] = l;
}

// ============================================================
// pipelined bf16 MMA GEMM (cp.async + ldmatrix, 2-stage)
// WHICH: 0 = gemm1 (g_A1,g_B1 -> g_h, +bias)
//        1 = sim   (g_feat2,g_mem2 -> Cout, N-bounded)
//        2 = gemm2 (g_A2,g_B2 -> g_feat, +bias)
// ============================================================
__device__ __forceinline__ void mma16816(float c[4],
    unsigned a0, unsigned a1, unsigned a2, unsigned a3,
    unsigned b0, unsigned b1)
{
    asm volatile(
        "mma.sync.aligned.m16n8k16.row.col.f32.bf16.bf16.f32 "
        "{%0,%1,%2,%3},{%4,%5,%6,%7},{%8,%9},{%0,%1,%2,%3};\n"
        : "+f"(c[0]), "+f"(c[1]), "+f"(c[2]), "+f"(c[3])
        : "r"(a0), "r"(a1), "r"(a2), "r"(a3), "r"(b0), "r"(b1));
}

__device__ __forceinline__ void cp_async16(void* dst, const void* src)
{
    unsigned s = (unsigned)__cvta_generic_to_shared(dst);
    asm volatile("cp.async.cg.shared.global [%0], [%1], 16;\n" :: "r"(s), "l"(src));
}
__device__ __forceinline__ void cp_commit() { asm volatile("cp.async.commit_group;\n"); }
__device__ __forceinline__ void cp_wait1() { asm volatile("cp.async.wait_group 1;\n"); }

__device__ __forceinline__ void ldsm_x4(unsigned& r0, unsigned& r1,
                                        unsigned& r2, unsigned& r3, const void* p)
{
    unsigned a = (unsigned)__cvta_generic_to_shared(p);
    asm volatile("ldmatrix.sync.aligned.m8n8.x4.shared.b16 {%0,%1,%2,%3}, [%4];\n"
        : "=r"(r0), "=r"(r1), "=r"(r2), "=r"(r3) : "r"(a));
}

template<int BN, int KP, int NK, int WHICH>
__global__ __launch_bounds__(256) void mma_gemm_kernel(
    float* __restrict__ Cout, const float* __restrict__ bias)
{
    constexpr int BM = 128, BK = 32;
    constexpr int LDS_ = 40;              // 80B row stride, conflict-free
    constexpr int WTN = BN / 4;
    constexpr int NTI = WTN / 8;
    constexpr int BCH = BN / 64;          // B 16B-chunks per thread (1 or 2)
    constexpr int Nreal = (WHICH == 0) ? DMLP : (WHICH == 1 ? NCLS : FD);
    constexpr int ldc   = Nreal;

    const __nv_bfloat16* __restrict__ A =
        (WHICH == 0) ? g_A1 : (WHICH == 1 ? g_feat2 : g_A2);
    const __nv_bfloat16* __restrict__ B =
        (WHICH == 0) ? g_B1 : (WHICH == 1 ? g_mem2 : g_B2);
    float* __restrict__ C = (WHICH == 0) ? g_h : (WHICH == 1 ? Cout : g_feat);

    __shared__ __align__(16) __nv_bfloat16 As[2][BM * LDS_];
    __shared__ __align__(16) __nv_bfloat16 Bs[2][BN * LDS_];

    const int tid = threadIdx.x;
    const int wid = tid >> 5, lane = tid & 31;
    const int wm = wid >> 2, wn = wid & 3;
    const int bm = blockIdx.y * BM;
    const int bn = blockIdx.x * BN;

    // cp.async source/dest indexing
    const int lr = tid >> 2, lk = (tid & 3) * 8;          // A: 128 rows x 4 chunks
    auto load_stage = [&](int kt, int s) {
        const __nv_bfloat16* asrc = A + (size_t)(bm + lr) * KP + kt * BK + lk;
        cp_async16(&As[s][lr * LDS_ + lk], asrc);
        cp_async16(&As[s][(lr + 64) * LDS_ + lk], asrc + (size_t)64 * KP);
#pragma unroll
        for (int i = 0; i < BCH; i++) {
            int r = lr + i * 64;
            int gn = bn + r;
            if (WHICH == 1) gn = (gn < NCLS) ? gn : (NCLS - 1);
            cp_async16(&Bs[s][r * LDS_ + lk], B + (size_t)gn * KP + kt * BK + lk);
        }
    };

    float acc[4][NTI][4];
#pragma unroll
    for (int i = 0; i < 4; i++)
#pragma unroll
        for (int j = 0; j < NTI; j++)
#pragma unroll
            for (int t = 0; t < 4; t++) acc[i][j][t] = 0.f;

    load_stage(0, 0);
    cp_commit();

    const int arow = lane & 15, ahalf = (lane >> 4) * 8;
    const int bl = lane & 7, bsel = lane >> 3;

    for (int kt = 0; kt < NK; kt++) {
        const int s = kt & 1;
        if (kt + 1 < NK) load_stage(kt + 1, s ^ 1);
        cp_commit();
        cp_wait1();
        __syncthreads();

#pragma unroll
        for (int ks = 0; ks < 2; ks++) {
            const int k0 = ks * 16;
            unsigned af[4][4];
#pragma unroll
            for (int i = 0; i < 4; i++)
                ldsm_x4(af[i][0], af[i][1], af[i][2], af[i][3],
                        &As[s][(wm * 64 + i * 16 + arow) * LDS_ + k0 + ahalf]);
            unsigned bfr[NTI][2];
#pragma unroll
            for (int p = 0; p < NTI / 2; p++) {
                int n = wn * WTN + (p * 2 + (bsel >> 1)) * 8 + bl;
                ldsm_x4(bfr[p * 2][0], bfr[p * 2][1], bfr[p * 2 + 1][0], bfr[p * 2 + 1][1],
                        &Bs[s][n * LDS_ + k0 + (bsel & 1) * 8]);
            }
#pragma unroll
            for (int i = 0; i < 4; i++)
#pragma unroll
                for (int j = 0; j < NTI; j++)
                    mma16816(acc[i][j], af[i][0], af[i][1], af[i][2], af[i][3],
                             bfr[j][0], bfr[j][1]);
        }
        __syncthreads();
    }

    const int g = lane >> 2, q2 = (lane & 3) * 2;
#pragma unroll
    for (int i = 0; i < 4; i++) {
        int m0 = bm + wm * 64 + i * 16 + g;
#pragma unroll
        for (int j = 0; j < NTI; j++) {
            int n0 = bn + wn * WTN + j * 8 + q2;
            if (WHICH != 1 || n0 < Nreal) {
                float b0 = 0.f, b1 = 0.f;
                if (WHICH != 1) { b0 = bias[n0]; b1 = bias[n0 + 1]; }
                *(float2*)(C + (size_t)m0 * ldc + n0) =
                    make_float2(acc[i][j][0] + b0, acc[i][j][1] + b1);
                *(float2*)(C + (size_t)(m0 + 8) * ldc + n0) =
                    make_float2(acc[i][j][2] + b0, acc[i][j][3] + b1);
            }
        }
    }
}

// ============================================================
// BN stats
// ============================================================
__global__ __launch_bounds__(512) void bn_partial_kernel()
{
    const int b = blockIdx.x, c = threadIdx.x;
    float s = 0.f, ss = 0.f;
#pragma unroll
    for (int r = 0; r < 16; r++) {
        float v = g_h[(size_t)(b * 16 + r) * DMLP + c];
        s += v; ss += v * v;
    }
    g_psum[b * DMLP + c] = s;
    g_psq[b * DMLP + c] = ss;
}

__global__ __launch_bounds__(512) void bn_final_kernel(
    const float* __restrict__ gamma, const float* __restrict__ beta)
{
    const int c = threadIdx.x;
    float s = 0.f, ss = 0.f;
#pragma unroll 8
    for (int b = 0; b < 256; b++) { s += g_psum[b * DMLP + c]; ss += g_psq[b * DMLP + c]; }
    float mu = s * (1.0f / NSAMP);
    float var = ss * (1.0f / NSAMP) - mu * mu;
    float sc = gamma[c] * rsqrtf(var + 1e-5f);
    g_scale[c] = sc;
    g_shift[c] = beta[c] - mu * sc;
}

// ============================================================
// row L2 normalize g_feat in place (warp per row)
// ============================================================
__global__ __launch_bounds__(256) void norm_kernel()
{
    const int w = threadIdx.x >> 5, lane = threadIdx.x & 31;
    const int row = blockIdx.x * 8 + w;
    float* p = g_feat + (size_t)row * FD;
    float4 v0 = *(float4*)(p + lane * 4);
    float4 v1 = *(float4*)(p + 128 + lane * 4);
    float ssq = v0.x * v0.x + v0.y * v0.y + v0.z * v0.z + v0.w * v0.w
              + v1.x * v1.x + v1.y * v1.y + v1.z * v1.z + v1.w * v1.w;
#pragma unroll
    for (int o = 16; o; o >>= 1) ssq += __shfl_xor_sync(0xffffffffu, ssq, o);
    float inv = 1.0f / fmaxf(sqrtf(ssq), 1e-12f);
    v0.x *= inv; v0.y *= inv; v0.z *= inv; v0.w *= inv;
    v1.x *= inv; v1.y *= inv; v1.z *= inv; v1.w *= inv;
    *(float4*)(p + lane * 4) = v0;
    *(float4*)(p + 128 + lane * 4) = v1;
}

// ============================================================
// Memory update: one warp per class row, in-order replay
// ============================================================
__global__ __launch_bounds__(256) void memupd_kernel(
    const int* __restrict__ label, const float* __restrict__ mem0)
{
    __shared__ int sl[NSAMP];
    const int tid = threadIdx.x;
    for (int i = tid; i < NSAMP; i += 256) sl[i] = label[i];
    __syncthreads();

    const int w = tid >> 5, lane = tid & 31;
    const int k = blockIdx.x * 8 + w;
    if (k >= NCLS) return;

    float pt[8];
#pragma unroll
    for (int j = 0; j < 8; j++) pt[j] = mem0[(size_t)k * FD + lane + j * 32];

    for (int base = 0; base < NSAMP; base += 32) {
        unsigned m = __ballot_sync(0xffffffffu, sl[base + lane] == k);
        while (m) {
            int b = __ffs(m) - 1;
            m &= m - 1;
            const float* f = g_feat + (size_t)(base + b) * FD;
            float ssq = 0.f;
#pragma unroll
            for (int j = 0; j < 8; j++) {
                pt[j] = 0.9f * pt[j] + 0.1f * f[lane + j * 32];
                ssq += pt[j] * pt[j];
            }
#pragma unroll
            for (int o = 16; o; o >>= 1) ssq += __shfl_xor_sync(0xffffffffu, ssq, o);
            float inv = 1.0f / fmaxf(sqrtf(ssq), 1e-12f);
#pragma unroll
            for (int j = 0; j < 8; j++) pt[j] *= inv;
        }
    }
#pragma unroll
    for (int j = 0; j < 8; j++) g_mem[(size_t)k * FD + lane + j * 32] = pt[j];
}

// ============================================================
// launch
// ============================================================
extern "C" void kernel_launch(void* const* d_in, const int* in_sizes, int n_in,
                              void* d_out, int out_size)
{
    const float* feat_in = (const float*)d_in[0];
    const int*   label   = (const int*)d_in[1];
    const float* W1      = (const float*)d_in[2];
    const float* b1      = (const float*)d_in[3];
    const float* gamma   = (const float*)d_in[4];
    const float* beta    = (const float*)d_in[5];
    const float* W2      = (const float*)d_in[6];
    const float* b2      = (const float*)d_in[7];
    const float* mem0    = (const float*)d_in[8];
    float* out = (float*)d_out;

    conv_A1_kernel<<<(NSAMP * DIN + 255) / 256, 256>>>(feat_in);
    conv_B1_kernel<<<(DIN * DMLP + 255) / 256, 256>>>(W1);
    conv_B2_kernel<<<(DMLP * FD + 255) / 256, 256>>>(W2);

    // GEMM1: g_h = feat_in @ W1 + b1
    mma_gemm_kernel<64, KP1, KP1 / 32, 0>
        <<<dim3(DMLP / 64, NSAMP / 128), 256>>>(nullptr, b1);

    bn_partial_kernel<<<256, 512>>>();
    bn_final_kernel<<<1, 512>>>(gamma, beta);
    conv_A2_kernel<<<(NSAMP * DMLP + 255) / 256, 256>>>();

    // GEMM2: g_feat = relu(bn(h)) @ W2 + b2  (raw)
    mma_gemm_kernel<64, KP2, KP2 / 32, 2>
        <<<dim3(FD / 64, NSAMP / 128), 256>>>(nullptr, b2);
    norm_kernel<<<NSAMP / 8, 256>>>();

    memupd_kernel<<<(NCLS + 7) / 8, 256>>>(label, mem0);

    conv_feat2_kernel<<<(NSAMP * FD + 255) / 256, 256>>>();
    conv_mem2_kernel<<<(NCLS * FD + 255) / 256, 256>>>();

    // Sim GEMM: out = feat @ mem^T
    mma_gemm_kernel<128, KPS, KPS / 32, 1>
        <<<dim3((NCLS + 127) / 128, NSAMP / 128), 256>>>(out, nullptr);
}